// round 6
// baseline (speedup 1.0000x reference)
#include <cuda_runtime.h>
#include <cuda_bf16.h>
#include <math.h>
#include <stdint.h>

// Problem constants (fixed instance)
#define NMAX   100000
#define EMAX   1600000
#define IN_DIM 256
#define HID    64      // HEADS*D1 = 8*8
#define HEADS  8
#define D1     8
#define NCLS   47
#define NC2P   48      // padded stride for layer-2 feature arrays
#define NEG_SLOPE 0.2f

// ---------------- device scratch (static allocation; no cudaMalloc) ----------------
__device__ int   g_is64;
__device__ int   g_dst32[EMAX];
__device__ int   g_src_sorted[EMAX];
__device__ int   g_deg[NMAX];
__device__ int   g_rowptr[NMAX + 1];
__device__ int   g_cur[NMAX];
__device__ int   g_bsum[128];           // >= ceil(NMAX/1024)=98 block sums

__device__ float g_fs1[(size_t)NMAX * HID];
__device__ float g_fd1[(size_t)NMAX * HID];
__device__ float g_h  [(size_t)NMAX * HID];
__device__ float g_fs2[(size_t)NMAX * NC2P];
__device__ float g_fd2[(size_t)NMAX * NC2P];

__device__ float g_Wc1[IN_DIM * 2 * HID];       // [256][128], pre-rounded to tf32
__device__ float g_bc1[2 * HID];
__device__ float g_Wc2[HID * 2 * NCLS];         // [64][94]  = [W2_src | W2_dst]
__device__ float g_bc2[2 * NCLS];

__device__ __forceinline__ float lrelu(float x) { return x > 0.f ? x : NEG_SLOPE * x; }
__device__ __forceinline__ float elu(float x)   { return x > 0.f ? x : expm1f(x); }
__device__ __forceinline__ float tf32r(float x) {
    uint32_t r; asm("cvt.rna.tf32.f32 %0, %1;" : "=r"(r) : "f"(x));
    return __uint_as_float(r);
}

// ---------------- index dtype detection ----------------
__global__ void detect_kernel(const int* __restrict__ srcW) {
    int ok64 = 1;
    #pragma unroll
    for (int i = 1; i < 16; i += 2) if (srcW[i] != 0) ok64 = 0;
    g_is64 = ok64;
}

__global__ void zero_deg_kernel(int N) {
    int v = blockIdx.x * blockDim.x + threadIdx.x;
    if (v < N) g_deg[v] = 0;
}

__global__ void convert_hist_kernel(const void* __restrict__ dstRaw, int E) {
    int e = blockIdx.x * blockDim.x + threadIdx.x;
    if (e >= E) return;
    int d = g_is64 ? (int)((const long long*)dstRaw)[e] : ((const int*)dstRaw)[e];
    g_dst32[e] = d;
    atomicAdd(&g_deg[d], 1);
}

// ---------------- 3-phase multi-block exclusive scan of g_deg -> g_rowptr ----------------
__global__ void scan_phase1(int N) {
    __shared__ int sh[1024];
    int t = threadIdx.x;
    int i = blockIdx.x * 1024 + t;
    int v = (i < N) ? g_deg[i] : 0;
    sh[t] = v;
    __syncthreads();
    #pragma unroll
    for (int off = 1; off < 1024; off <<= 1) {
        int x = (t >= off) ? sh[t - off] : 0;
        __syncthreads();
        sh[t] += x;
        __syncthreads();
    }
    if (i < N) g_rowptr[i] = sh[t] - v;
    if (t == 1023) g_bsum[blockIdx.x] = sh[1023];
}

__global__ void scan_phase2(int nb, int N) {
    __shared__ int sh[128];
    int t = threadIdx.x;
    int v = (t < nb) ? g_bsum[t] : 0;
    sh[t] = v;
    __syncthreads();
    #pragma unroll
    for (int off = 1; off < 128; off <<= 1) {
        int x = (t >= off) ? sh[t - off] : 0;
        __syncthreads();
        sh[t] += x;
        __syncthreads();
    }
    if (t < nb) g_bsum[t] = sh[t] - v;
    if (t == 127) g_rowptr[N] = sh[127];
}

__global__ void scan_phase3(int N) {
    int i = blockIdx.x * blockDim.x + threadIdx.x;
    if (i < N) {
        int r = g_rowptr[i] + g_bsum[i >> 10];
        g_rowptr[i] = r;
        g_cur[i] = r;
    }
}

__global__ void scatter_kernel(const void* __restrict__ srcRaw, int E) {
    int e = blockIdx.x * blockDim.x + threadIdx.x;
    if (e >= E) return;
    int s = g_is64 ? (int)((const long long*)srcRaw)[e] : ((const int*)srcRaw)[e];
    int d = g_dst32[e];
    int p = atomicAdd(&g_cur[d], 1);
    g_src_sorted[p] = s;
}

// ---------------- weight packing (Wc1 pre-rounded to tf32) ----------------
__global__ void combine1_kernel(const float* __restrict__ Ws, const float* __restrict__ bs,
                                const float* __restrict__ Wd, const float* __restrict__ bd) {
    int i = blockIdx.x * blockDim.x + threadIdx.x;
    int total = IN_DIM * 2 * HID;
    if (i < total) {
        int k = i / (2 * HID), c = i % (2 * HID);
        float v = (c < HID) ? Ws[k * HID + c] : Wd[k * HID + (c - HID)];
        g_Wc1[i] = tf32r(v);
    }
    if (i < 2 * HID) g_bc1[i] = (i < HID) ? bs[i] : bd[i - HID];
}

__global__ void combine2_kernel(const float* __restrict__ Ws, const float* __restrict__ bs,
                                const float* __restrict__ Wd, const float* __restrict__ bd) {
    int i = blockIdx.x * blockDim.x + threadIdx.x;
    int total = HID * 2 * NCLS;
    if (i < total) {
        int k = i / (2 * NCLS), c = i % (2 * NCLS);
        g_Wc2[i] = (c < NCLS) ? Ws[k * NCLS + c] : Wd[k * NCLS + (c - NCLS)];
    }
    if (i < 2 * NCLS) g_bc2[i] = (i < NCLS) ? bs[i] : bd[i - NCLS];
}

// ---------------- GEMM 1 (TF32 tensor cores, pre-rounded operands) ----------------
// 256 threads = 8 warps; block tile 128x128; warp tile 16x128; K-chunk 32, mma m16n8k8.
__global__ void gemm1_tc_kernel(const float* __restrict__ x, int M) {
    __shared__ float As[128][36];
    __shared__ float Bs[32][136];
    int tid  = threadIdx.x;
    int lane = tid & 31;
    int warp = tid >> 5;
    int row0 = blockIdx.x * 128;
    int warpRow = warp * 16;
    int gid = lane >> 2;
    int tig = lane & 3;

    float c[16][4];
    #pragma unroll
    for (int j = 0; j < 16; ++j)
        #pragma unroll
        for (int q = 0; q < 4; ++q) c[j][q] = 0.f;

    for (int k0 = 0; k0 < IN_DIM; k0 += 32) {
        // load A tile 128x32 (float4), round to tf32 at store time
        #pragma unroll
        for (int i = 0; i < 4; ++i) {
            int id = tid * 4 + i;
            int r = id >> 3, q = id & 7;
            int grow = row0 + r;
            float4 v = (grow < M)
                ? *(const float4*)(x + (size_t)grow * IN_DIM + k0 + q * 4)
                : make_float4(0.f, 0.f, 0.f, 0.f);
            v.x = tf32r(v.x); v.y = tf32r(v.y); v.z = tf32r(v.z); v.w = tf32r(v.w);
            *(float4*)&As[r][q * 4] = v;
        }
        // load B tile 32x128 (float4) — already tf32-rounded in g_Wc1
        #pragma unroll
        for (int i = 0; i < 4; ++i) {
            int id = tid * 4 + i;
            int r = id >> 5, q = id & 31;
            *(float4*)&Bs[r][q * 4] = *(const float4*)&g_Wc1[(k0 + r) * 128 + q * 4];
        }
        __syncthreads();
        #pragma unroll
        for (int kk = 0; kk < 32; kk += 8) {
            uint32_t a[4];
            a[0] = __float_as_uint(As[warpRow + gid    ][kk + tig    ]);
            a[1] = __float_as_uint(As[warpRow + gid + 8][kk + tig    ]);
            a[2] = __float_as_uint(As[warpRow + gid    ][kk + tig + 4]);
            a[3] = __float_as_uint(As[warpRow + gid + 8][kk + tig + 4]);
            #pragma unroll
            for (int j = 0; j < 16; ++j) {
                uint32_t b[2];
                b[0] = __float_as_uint(Bs[kk + tig    ][j * 8 + gid]);
                b[1] = __float_as_uint(Bs[kk + tig + 4][j * 8 + gid]);
                asm("mma.sync.aligned.m16n8k8.row.col.f32.tf32.tf32.f32 "
                    "{%0,%1,%2,%3}, {%4,%5,%6,%7}, {%8,%9}, {%0,%1,%2,%3};"
                    : "+f"(c[j][0]), "+f"(c[j][1]), "+f"(c[j][2]), "+f"(c[j][3])
                    : "r"(a[0]), "r"(a[1]), "r"(a[2]), "r"(a[3]),
                      "r"(b[0]), "r"(b[1]));
            }
        }
        __syncthreads();
    }
    int r0 = row0 + warpRow + gid;
    int r1 = r0 + 8;
    #pragma unroll
    for (int j = 0; j < 16; ++j) {
        int cb = j * 8 + tig * 2;
        float2 bv = *(const float2*)&g_bc1[cb];
        if (r0 < M) {
            float2 v = make_float2(c[j][0] + bv.x, c[j][1] + bv.y);
            if (cb < HID) *(float2*)&g_fs1[(size_t)r0 * HID + cb] = v;
            else          *(float2*)&g_fd1[(size_t)r0 * HID + cb - HID] = v;
        }
        if (r1 < M) {
            float2 v = make_float2(c[j][2] + bv.x, c[j][3] + bv.y);
            if (cb < HID) *(float2*)&g_fs1[(size_t)r1 * HID + cb] = v;
            else          *(float2*)&g_fd1[(size_t)r1 * HID + cb - HID] = v;
        }
    }
}

// ---------------- GEMM 2: h[M,64] @ Wc2[64,94] + bc2 -> fs2|fd2 (stride 48) ----------------
__global__ void gemm2_kernel(int M) {
    __shared__ float Hs[64][65];
    __shared__ float Ws[64][96];
    int tid = threadIdx.x;            // 256
    int tx = tid & 15, ty = tid >> 4;
    int row0 = blockIdx.x * 64;

    for (int idx = tid; idx < 64 * 2 * NCLS; idx += 256)
        Ws[idx / (2 * NCLS)][idx % (2 * NCLS)] = g_Wc2[idx];
    for (int idx = tid; idx < 64 * 64; idx += 256) {
        int r = idx >> 6, c = idx & 63;
        Hs[r][c] = (row0 + r < M) ? g_h[(size_t)(row0 + r) * HID + c] : 0.f;
    }
    __syncthreads();

    float acc[4][6];
    #pragma unroll
    for (int i = 0; i < 4; ++i)
        #pragma unroll
        for (int j = 0; j < 6; ++j) acc[i][j] = 0.f;

    #pragma unroll 8
    for (int k = 0; k < 64; ++k) {
        float a[4], b[6];
        #pragma unroll
        for (int i = 0; i < 4; ++i) a[i] = Hs[i * 16 + ty][k];
        #pragma unroll
        for (int j = 0; j < 6; ++j) b[j] = Ws[k][j * 16 + tx];
        #pragma unroll
        for (int i = 0; i < 4; ++i)
            #pragma unroll
            for (int j = 0; j < 6; ++j) acc[i][j] = fmaf(a[i], b[j], acc[i][j]);
    }
    #pragma unroll
    for (int i = 0; i < 4; ++i) {
        int grow = row0 + i * 16 + ty;
        if (grow >= M) continue;
        #pragma unroll
        for (int j = 0; j < 6; ++j) {
            int c = j * 16 + tx;
            if (c >= 2 * NCLS) continue;
            float v = acc[i][j] + g_bc2[c];
            if (c < NCLS) g_fs2[(size_t)grow * NC2P + c] = v;
            else          g_fd2[(size_t)grow * NC2P + (c - NCLS)] = v;
        }
    }
}

// ---------------- layer 1: warp/node, 2 dims/lane, 2-way unrolled online softmax ----------------
__global__ void layer1_kernel(int N, const float* __restrict__ attn1,
                              const float* __restrict__ bias1) {
    int w = (blockIdx.x * blockDim.x + threadIdx.x) >> 5;
    int lane = threadIdx.x & 31;
    if (w >= N) return;
    int start = g_rowptr[w], end = g_rowptr[w + 1];
    int j0 = 2 * lane;                               // dims j0, j0+1 (head = lane>>2)

    float2 bv = *(const float2*)&bias1[j0];
    if (start == end) {
        float2 o = make_float2(elu(bv.x), elu(bv.y));
        *(float2*)&g_h[(size_t)w * HID + j0] = o;
        return;
    }
    float2 fdv = *(const float2*)&g_fd1[(size_t)w * HID + j0];
    float2 att = *(const float2*)&attn1[j0];

    // two independent online-softmax states (A: even slots + tail, B: odd slots)
    float mA = -INFINITY, sA = 0.f, axA = 0.f, ayA = 0.f;
    float mB = -INFINITY, sB = 0.f, axB = 0.f, ayB = 0.f;

    int p = start;
    for (; p + 2 <= end; p += 2) {
        int u0 = g_src_sorted[p];
        int u1 = g_src_sorted[p + 1];
        float2 fA = *(const float2*)&g_fs1[(size_t)u0 * HID + j0];
        float2 fB = *(const float2*)&g_fs1[(size_t)u1 * HID + j0];
        float tA = lrelu(fA.x + fdv.x) * att.x + lrelu(fA.y + fdv.y) * att.y;
        float tB = lrelu(fB.x + fdv.x) * att.x + lrelu(fB.y + fdv.y) * att.y;
        tA += __shfl_xor_sync(0xffffffffu, tA, 1);
        tB += __shfl_xor_sync(0xffffffffu, tB, 1);
        tA += __shfl_xor_sync(0xffffffffu, tA, 2);
        tB += __shfl_xor_sync(0xffffffffu, tB, 2);
        float edA = __expf(0.f - fabsf(tA - mA));
        float edB = __expf(0.f - fabsf(tB - mB));
        bool upA = tA > mA, upB = tB > mB;
        float scA = upA ? edA : 1.f, wtA = upA ? 1.f : edA;
        float scB = upB ? edB : 1.f, wtB = upB ? 1.f : edB;
        mA = fmaxf(mA, tA);
        mB = fmaxf(mB, tB);
        sA = fmaf(sA, scA, wtA);
        sB = fmaf(sB, scB, wtB);
        axA = fmaf(axA, scA, wtA * fA.x);
        axB = fmaf(axB, scB, wtB * fB.x);
        ayA = fmaf(ayA, scA, wtA * fA.y);
        ayB = fmaf(ayB, scB, wtB * fB.y);
    }
    if (p < end) {
        int u0 = g_src_sorted[p];
        float2 fA = *(const float2*)&g_fs1[(size_t)u0 * HID + j0];
        float tA = lrelu(fA.x + fdv.x) * att.x + lrelu(fA.y + fdv.y) * att.y;
        tA += __shfl_xor_sync(0xffffffffu, tA, 1);
        tA += __shfl_xor_sync(0xffffffffu, tA, 2);
        float edA = __expf(0.f - fabsf(tA - mA));
        bool upA = tA > mA;
        float scA = upA ? edA : 1.f, wtA = upA ? 1.f : edA;
        mA = fmaxf(mA, tA);
        sA = fmaf(sA, scA, wtA);
        axA = fmaf(axA, scA, wtA * fA.x);
        ayA = fmaf(ayA, scA, wtA * fA.y);
    }
    // merge B into A (A is always non-empty; empty B: exp(-inf)=0)
    float m = fmaxf(mA, mB);
    float eA = __expf(mA - m);
    float eB = __expf(mB - m);
    float s    = sA * eA + sB * eB;
    float accx = axA * eA + axB * eB;
    float accy = ayA * eA + ayB * eB;

    float inv = 1.f / s;
    float2 o = make_float2(elu(accx * inv + bv.x), elu(accy * inv + bv.y));
    *(float2*)&g_h[(size_t)w * HID + j0] = o;
}

// ---------------- layer 2: warp/node, 2 classes/lane, 2-way unrolled online softmax ----------------
__global__ void layer2_kernel(int N, const float* __restrict__ attn2,
                              const float* __restrict__ bias2,
                              float* __restrict__ out) {
    int w = (blockIdx.x * blockDim.x + threadIdx.x) >> 5;
    int lane = threadIdx.x & 31;
    if (w >= N) return;
    int start = g_rowptr[w], end = g_rowptr[w + 1];
    int j0 = 2 * lane;
    int off = j0 < 46 ? j0 : 46;                     // clamped, even -> aligned float2
    bool m0 = (j0 < NCLS), m1 = (j0 + 1 < NCLS);

    float b0 = m0 ? bias2[j0] : 0.f;
    float b1 = m1 ? bias2[j0 + 1] : 0.f;
    if (start == end) {
        if (m0) out[(size_t)w * NCLS + j0] = b0;
        if (m1) out[(size_t)w * NCLS + j0 + 1] = b1;
        return;
    }
    float2 fdr = *(const float2*)&g_fd2[(size_t)w * NC2P + off];
    float fdv0 = m0 ? fdr.x : 0.f;
    float fdv1 = m1 ? fdr.y : 0.f;
    float att0 = m0 ? attn2[j0] : 0.f;
    float att1 = m1 ? attn2[j0 + 1] : 0.f;

    float mA = -INFINITY, sA = 0.f, a0A = 0.f, a1A = 0.f;
    float mB = -INFINITY, sB = 0.f, a0B = 0.f, a1B = 0.f;

    int p = start;
    for (; p + 2 <= end; p += 2) {
        int u0 = g_src_sorted[p];
        int u1 = g_src_sorted[p + 1];
        float2 frA = *(const float2*)&g_fs2[(size_t)u0 * NC2P + off];
        float2 frB = *(const float2*)&g_fs2[(size_t)u1 * NC2P + off];
        float f0A = m0 ? frA.x : 0.f, f1A = m1 ? frA.y : 0.f;
        float f0B = m0 ? frB.x : 0.f, f1B = m1 ? frB.y : 0.f;
        float tA = lrelu(f0A + fdv0) * att0 + lrelu(f1A + fdv1) * att1;
        float tB = lrelu(f0B + fdv0) * att0 + lrelu(f1B + fdv1) * att1;
        tA += __shfl_xor_sync(0xffffffffu, tA, 1);
        tB += __shfl_xor_sync(0xffffffffu, tB, 1);
        tA += __shfl_xor_sync(0xffffffffu, tA, 2);
        tB += __shfl_xor_sync(0xffffffffu, tB, 2);
        tA += __shfl_xor_sync(0xffffffffu, tA, 4);
        tB += __shfl_xor_sync(0xffffffffu, tB, 4);
        tA += __shfl_xor_sync(0xffffffffu, tA, 8);
        tB += __shfl_xor_sync(0xffffffffu, tB, 8);
        tA += __shfl_xor_sync(0xffffffffu, tA, 16);
        tB += __shfl_xor_sync(0xffffffffu, tB, 16);
        float edA = __expf(0.f - fabsf(tA - mA));
        float edB = __expf(0.f - fabsf(tB - mB));
        bool upA = tA > mA, upB = tB > mB;
        float scA = upA ? edA : 1.f, wtA = upA ? 1.f : edA;
        float scB = upB ? edB : 1.f, wtB = upB ? 1.f : edB;
        mA = fmaxf(mA, tA);
        mB = fmaxf(mB, tB);
        sA = fmaf(sA, scA, wtA);
        sB = fmaf(sB, scB, wtB);
        a0A = fmaf(a0A, scA, wtA * f0A);
        a0B = fmaf(a0B, scB, wtB * f0B);
        a1A = fmaf(a1A, scA, wtA * f1A);
        a1B = fmaf(a1B, scB, wtB * f1B);
    }
    if (p < end) {
        int u0 = g_src_sorted[p];
        float2 frA = *(const float2*)&g_fs2[(size_t)u0 * NC2P + off];
        float f0A = m0 ? frA.x : 0.f, f1A = m1 ? frA.y : 0.f;
        float tA = lrelu(f0A + fdv0) * att0 + lrelu(f1A + fdv1) * att1;
        tA += __shfl_xor_sync(0xffffffffu, tA, 1);
        tA += __shfl_xor_sync(0xffffffffu, tA, 2);
        tA += __shfl_xor_sync(0xffffffffu, tA, 4);
        tA += __shfl_xor_sync(0xffffffffu, tA, 8);
        tA += __shfl_xor_sync(0xffffffffu, tA, 16);
        float edA = __expf(0.f - fabsf(tA - mA));
        bool upA = tA > mA;
        float scA = upA ? edA : 1.f, wtA = upA ? 1.f : edA;
        mA = fmaxf(mA, tA);
        sA = fmaf(sA, scA, wtA);
        a0A = fmaf(a0A, scA, wtA * f0A);
        a1A = fmaf(a1A, scA, wtA * f1A);
    }
    float m = fmaxf(mA, mB);
    float eA = __expf(mA - m);
    float eB = __expf(mB - m);
    float s    = sA * eA + sB * eB;
    float acc0 = a0A * eA + a0B * eB;
    float acc1 = a1A * eA + a1B * eB;

    float inv = 1.f / s;
    if (m0) out[(size_t)w * NCLS + j0]     = acc0 * inv + b0;
    if (m1) out[(size_t)w * NCLS + j0 + 1] = acc1 * inv + b1;
}

// ---------------- launch ----------------
extern "C" void kernel_launch(void* const* d_in, const int* in_sizes, int n_in,
                              void* d_out, int out_size) {
    const float* x      = (const float*)d_in[0];
    const void*  srcRaw = d_in[1];
    const void*  dstRaw = d_in[2];
    const float* W1s = (const float*)d_in[3];
    const float* b1s = (const float*)d_in[4];
    const float* W1d = (const float*)d_in[5];
    const float* b1d = (const float*)d_in[6];
    const float* attn1 = (const float*)d_in[7];
    const float* bias1 = (const float*)d_in[8];
    const float* W2s = (const float*)d_in[9];
    const float* b2s = (const float*)d_in[10];
    const float* W2d = (const float*)d_in[11];
    const float* b2d = (const float*)d_in[12];
    const float* attn2 = (const float*)d_in[13];
    const float* bias2 = (const float*)d_in[14];
    float* out = (float*)d_out;

    int N = in_sizes[0] / IN_DIM;   // 100000
    int E = in_sizes[1];            // 1600000
    int nb = (N + 1023) >> 10;      // scan blocks (98)

    detect_kernel<<<1, 1>>>((const int*)srcRaw);
    zero_deg_kernel<<<(N + 255) / 256, 256>>>(N);
    convert_hist_kernel<<<(E + 255) / 256, 256>>>(dstRaw, E);
    scan_phase1<<<nb, 1024>>>(N);
    scan_phase2<<<1, 128>>>(nb, N);
    scan_phase3<<<(N + 255) / 256, 256>>>(N);
    scatter_kernel<<<(E + 255) / 256, 256>>>(srcRaw, E);

    combine1_kernel<<<(IN_DIM * 2 * HID + 255) / 256, 256>>>(W1s, b1s, W1d, b1d);
    combine2_kernel<<<(HID * 2 * NCLS + 255) / 256, 256>>>(W2s, b2s, W2d, b2d);

    gemm1_tc_kernel<<<(N + 127) / 128, 256>>>(x, N);
    layer1_kernel<<<(N + 7) / 8, 256>>>(N, attn1, bias1);
    gemm2_kernel<<<(N + 63) / 64, 256>>>(N);
    layer2_kernel<<<(N + 7) / 8, 256>>>(N, attn2, bias2, out);
}

// round 8
// speedup vs baseline: 1.0397x; 1.0397x over previous
#include <cuda_runtime.h>
#include <cuda_bf16.h>
#include <math.h>
#include <stdint.h>

// Problem constants (fixed instance)
#define NMAX   100000
#define EMAX   1600000
#define IN_DIM 256
#define HID    64      // HEADS*D1 = 8*8
#define HEADS  8
#define D1     8
#define NCLS   47
#define NC2P   48      // padded stride for layer-2 feature arrays
#define NEG_SLOPE 0.2f

// ---------------- device scratch (static allocation; no cudaMalloc) ----------------
__device__ int   g_is64;
__device__ int   g_dst32[EMAX];
__device__ int   g_src_sorted[EMAX];
__device__ int   g_deg[NMAX];
__device__ int   g_rowptr[NMAX + 1];
__device__ int   g_cur[NMAX];
__device__ int   g_bsum[128];           // >= ceil(NMAX/1024)=98 block sums

__device__ float g_fs1[(size_t)NMAX * HID];
__device__ float g_fd1[(size_t)NMAX * HID];
__device__ float g_h  [(size_t)NMAX * HID];
__device__ float g_fs2[(size_t)NMAX * NC2P];
__device__ float g_fd2[(size_t)NMAX * NC2P];

__device__ float g_Wc1[IN_DIM * 2 * HID];       // [256][128], pre-rounded to tf32
__device__ float g_bc1[2 * HID];
__device__ float g_Wc2[HID * 2 * NCLS];         // [64][94]  = [W2_src | W2_dst]
__device__ float g_bc2[2 * NCLS];

__device__ __forceinline__ float lrelu(float x) { return x > 0.f ? x : NEG_SLOPE * x; }
__device__ __forceinline__ float elu(float x)   { return x > 0.f ? x : expm1f(x); }
__device__ __forceinline__ float tf32r(float x) {
    uint32_t r; asm("cvt.rna.tf32.f32 %0, %1;" : "=r"(r) : "f"(x));
    return __uint_as_float(r);
}

// ---------------- index dtype detection ----------------
__global__ void detect_kernel(const int* __restrict__ srcW) {
    int ok64 = 1;
    #pragma unroll
    for (int i = 1; i < 16; i += 2) if (srcW[i] != 0) ok64 = 0;
    g_is64 = ok64;
}

__global__ void zero_deg_kernel(int N) {
    int v = blockIdx.x * blockDim.x + threadIdx.x;
    if (v < N) g_deg[v] = 0;
}

__global__ void convert_hist_kernel(const void* __restrict__ dstRaw, int E) {
    int e = blockIdx.x * blockDim.x + threadIdx.x;
    if (e >= E) return;
    int d = g_is64 ? (int)((const long long*)dstRaw)[e] : ((const int*)dstRaw)[e];
    g_dst32[e] = d;
    atomicAdd(&g_deg[d], 1);
}

// ---------------- 3-phase multi-block exclusive scan of g_deg -> g_rowptr ----------------
__global__ void scan_phase1(int N) {
    __shared__ int sh[1024];
    int t = threadIdx.x;
    int i = blockIdx.x * 1024 + t;
    int v = (i < N) ? g_deg[i] : 0;
    sh[t] = v;
    __syncthreads();
    #pragma unroll
    for (int off = 1; off < 1024; off <<= 1) {
        int x = (t >= off) ? sh[t - off] : 0;
        __syncthreads();
        sh[t] += x;
        __syncthreads();
    }
    if (i < N) g_rowptr[i] = sh[t] - v;
    if (t == 1023) g_bsum[blockIdx.x] = sh[1023];
}

__global__ void scan_phase2(int nb, int N) {
    __shared__ int sh[128];
    int t = threadIdx.x;
    int v = (t < nb) ? g_bsum[t] : 0;
    sh[t] = v;
    __syncthreads();
    #pragma unroll
    for (int off = 1; off < 128; off <<= 1) {
        int x = (t >= off) ? sh[t - off] : 0;
        __syncthreads();
        sh[t] += x;
        __syncthreads();
    }
    if (t < nb) g_bsum[t] = sh[t] - v;
    if (t == 127) g_rowptr[N] = sh[127];
}

__global__ void scan_phase3(int N) {
    int i = blockIdx.x * blockDim.x + threadIdx.x;
    if (i < N) {
        int r = g_rowptr[i] + g_bsum[i >> 10];
        g_rowptr[i] = r;
        g_cur[i] = r;
    }
}

__global__ void scatter_kernel(const void* __restrict__ srcRaw, int E) {
    int e = blockIdx.x * blockDim.x + threadIdx.x;
    if (e >= E) return;
    int s = g_is64 ? (int)((const long long*)srcRaw)[e] : ((const int*)srcRaw)[e];
    int d = g_dst32[e];
    int p = atomicAdd(&g_cur[d], 1);
    g_src_sorted[p] = s;
}

// ---------------- weight packing (Wc1 pre-rounded to tf32) ----------------
__global__ void combine1_kernel(const float* __restrict__ Ws, const float* __restrict__ bs,
                                const float* __restrict__ Wd, const float* __restrict__ bd) {
    int i = blockIdx.x * blockDim.x + threadIdx.x;
    int total = IN_DIM * 2 * HID;
    if (i < total) {
        int k = i / (2 * HID), c = i % (2 * HID);
        float v = (c < HID) ? Ws[k * HID + c] : Wd[k * HID + (c - HID)];
        g_Wc1[i] = tf32r(v);
    }
    if (i < 2 * HID) g_bc1[i] = (i < HID) ? bs[i] : bd[i - HID];
}

__global__ void combine2_kernel(const float* __restrict__ Ws, const float* __restrict__ bs,
                                const float* __restrict__ Wd, const float* __restrict__ bd) {
    int i = blockIdx.x * blockDim.x + threadIdx.x;
    int total = HID * 2 * NCLS;
    if (i < total) {
        int k = i / (2 * NCLS), c = i % (2 * NCLS);
        g_Wc2[i] = (c < NCLS) ? Ws[k * NCLS + c] : Wd[k * NCLS + (c - NCLS)];
    }
    if (i < 2 * NCLS) g_bc2[i] = (i < NCLS) ? bs[i] : bd[i - NCLS];
}

// ---------------- GEMM 1 (TF32 tensor cores, pre-rounded operands) ----------------
__global__ void gemm1_tc_kernel(const float* __restrict__ x, int M) {
    __shared__ float As[128][36];
    __shared__ float Bs[32][136];
    int tid  = threadIdx.x;
    int lane = tid & 31;
    int warp = tid >> 5;
    int row0 = blockIdx.x * 128;
    int warpRow = warp * 16;
    int gid = lane >> 2;
    int tig = lane & 3;

    float c[16][4];
    #pragma unroll
    for (int j = 0; j < 16; ++j)
        #pragma unroll
        for (int q = 0; q < 4; ++q) c[j][q] = 0.f;

    for (int k0 = 0; k0 < IN_DIM; k0 += 32) {
        #pragma unroll
        for (int i = 0; i < 4; ++i) {
            int id = tid * 4 + i;
            int r = id >> 3, q = id & 7;
            int grow = row0 + r;
            float4 v = (grow < M)
                ? *(const float4*)(x + (size_t)grow * IN_DIM + k0 + q * 4)
                : make_float4(0.f, 0.f, 0.f, 0.f);
            v.x = tf32r(v.x); v.y = tf32r(v.y); v.z = tf32r(v.z); v.w = tf32r(v.w);
            *(float4*)&As[r][q * 4] = v;
        }
        #pragma unroll
        for (int i = 0; i < 4; ++i) {
            int id = tid * 4 + i;
            int r = id >> 5, q = id & 31;
            *(float4*)&Bs[r][q * 4] = *(const float4*)&g_Wc1[(k0 + r) * 128 + q * 4];
        }
        __syncthreads();
        #pragma unroll
        for (int kk = 0; kk < 32; kk += 8) {
            uint32_t a[4];
            a[0] = __float_as_uint(As[warpRow + gid    ][kk + tig    ]);
            a[1] = __float_as_uint(As[warpRow + gid + 8][kk + tig    ]);
            a[2] = __float_as_uint(As[warpRow + gid    ][kk + tig + 4]);
            a[3] = __float_as_uint(As[warpRow + gid + 8][kk + tig + 4]);
            #pragma unroll
            for (int j = 0; j < 16; ++j) {
                uint32_t b[2];
                b[0] = __float_as_uint(Bs[kk + tig    ][j * 8 + gid]);
                b[1] = __float_as_uint(Bs[kk + tig + 4][j * 8 + gid]);
                asm("mma.sync.aligned.m16n8k8.row.col.f32.tf32.tf32.f32 "
                    "{%0,%1,%2,%3}, {%4,%5,%6,%7}, {%8,%9}, {%0,%1,%2,%3};"
                    : "+f"(c[j][0]), "+f"(c[j][1]), "+f"(c[j][2]), "+f"(c[j][3])
                    : "r"(a[0]), "r"(a[1]), "r"(a[2]), "r"(a[3]),
                      "r"(b[0]), "r"(b[1]));
            }
        }
        __syncthreads();
    }
    int r0 = row0 + warpRow + gid;
    int r1 = r0 + 8;
    #pragma unroll
    for (int j = 0; j < 16; ++j) {
        int cb = j * 8 + tig * 2;
        float2 bv = *(const float2*)&g_bc1[cb];
        if (r0 < M) {
            float2 v = make_float2(c[j][0] + bv.x, c[j][1] + bv.y);
            if (cb < HID) *(float2*)&g_fs1[(size_t)r0 * HID + cb] = v;
            else          *(float2*)&g_fd1[(size_t)r0 * HID + cb - HID] = v;
        }
        if (r1 < M) {
            float2 v = make_float2(c[j][2] + bv.x, c[j][3] + bv.y);
            if (cb < HID) *(float2*)&g_fs1[(size_t)r1 * HID + cb] = v;
            else          *(float2*)&g_fd1[(size_t)r1 * HID + cb - HID] = v;
        }
    }
}

// ---------------- GEMM 2: h[M,64] @ Wc2[64,94] + bc2 -> fs2|fd2 (stride 48) ----------------
__global__ void gemm2_kernel(int M) {
    __shared__ float Hs[64][65];
    __shared__ float Ws[64][96];
    int tid = threadIdx.x;            // 256
    int tx = tid & 15, ty = tid >> 4;
    int row0 = blockIdx.x * 64;

    for (int idx = tid; idx < 64 * 2 * NCLS; idx += 256)
        Ws[idx / (2 * NCLS)][idx % (2 * NCLS)] = g_Wc2[idx];
    for (int idx = tid; idx < 64 * 64; idx += 256) {
        int r = idx >> 6, c = idx & 63;
        Hs[r][c] = (row0 + r < M) ? g_h[(size_t)(row0 + r) * HID + c] : 0.f;
    }
    __syncthreads();

    float acc[4][6];
    #pragma unroll
    for (int i = 0; i < 4; ++i)
        #pragma unroll
        for (int j = 0; j < 6; ++j) acc[i][j] = 0.f;

    #pragma unroll 8
    for (int k = 0; k < 64; ++k) {
        float a[4], b[6];
        #pragma unroll
        for (int i = 0; i < 4; ++i) a[i] = Hs[i * 16 + ty][k];
        #pragma unroll
        for (int j = 0; j < 6; ++j) b[j] = Ws[k][j * 16 + tx];
        #pragma unroll
        for (int i = 0; i < 4; ++i)
            #pragma unroll
            for (int j = 0; j < 6; ++j) acc[i][j] = fmaf(a[i], b[j], acc[i][j]);
    }
    #pragma unroll
    for (int i = 0; i < 4; ++i) {
        int grow = row0 + i * 16 + ty;
        if (grow >= M) continue;
        #pragma unroll
        for (int j = 0; j < 6; ++j) {
            int c = j * 16 + tx;
            if (c >= 2 * NCLS) continue;
            float v = acc[i][j] + g_bc2[c];
            if (c < NCLS) g_fs2[(size_t)grow * NC2P + c] = v;
            else          g_fd2[(size_t)grow * NC2P + (c - NCLS)] = v;
        }
    }
}

// ---------------- layer 1: HALF-warp per node, 4 dims/lane (float4), head = 2 lanes ----------------
__global__ void layer1_kernel(int N, const float* __restrict__ attn1,
                              const float* __restrict__ bias1) {
    int gwarp = (blockIdx.x * blockDim.x + threadIdx.x) >> 5;
    int lane  = threadIdx.x & 31;
    int half  = lane >> 4;                   // 0 or 1
    int l16   = lane & 15;
    int w     = gwarp * 2 + half;
    if (w >= N) return;
    unsigned hmask = half ? 0xFFFF0000u : 0x0000FFFFu;
    int start = g_rowptr[w], end = g_rowptr[w + 1];
    int j0 = 4 * l16;                        // dims j0..j0+3 (head = l16>>1)

    float4 bv = *(const float4*)&bias1[j0];
    if (start == end) {
        float4 o = make_float4(elu(bv.x), elu(bv.y), elu(bv.z), elu(bv.w));
        *(float4*)&g_h[(size_t)w * HID + j0] = o;
        return;
    }
    float4 fdv = *(const float4*)&g_fd1[(size_t)w * HID + j0];
    float4 att = *(const float4*)&attn1[j0];

    float mx = -INFINITY, s = 0.f;
    float ax = 0.f, ay = 0.f, az = 0.f, aw = 0.f;

    for (int p = start; p < end; ++p) {
        int u = g_src_sorted[p];
        float4 f = *(const float4*)&g_fs1[(size_t)u * HID + j0];
        float t = lrelu(f.x + fdv.x) * att.x + lrelu(f.y + fdv.y) * att.y
                + lrelu(f.z + fdv.z) * att.z + lrelu(f.w + fdv.w) * att.w;
        t += __shfl_xor_sync(hmask, t, 1);   // head score (2 lanes per head)
        float ed = __expf(0.f - fabsf(t - mx));
        bool up = t > mx;
        float sc = up ? ed : 1.f;
        float wt = up ? 1.f : ed;
        mx = fmaxf(mx, t);
        s = fmaf(s, sc, wt);
        ax = fmaf(ax, sc, wt * f.x);
        ay = fmaf(ay, sc, wt * f.y);
        az = fmaf(az, sc, wt * f.z);
        aw = fmaf(aw, sc, wt * f.w);
    }
    float inv = 1.f / s;
    float4 o = make_float4(elu(ax * inv + bv.x), elu(ay * inv + bv.y),
                           elu(az * inv + bv.z), elu(aw * inv + bv.w));
    *(float4*)&g_h[(size_t)w * HID + j0] = o;
}

// ---------------- layer 2: warp/node, 2 classes per lane (padded stride 48) ----------------
__global__ void layer2_kernel(int N, const float* __restrict__ attn2,
                              const float* __restrict__ bias2,
                              float* __restrict__ out) {
    int w = (blockIdx.x * blockDim.x + threadIdx.x) >> 5;
    int lane = threadIdx.x & 31;
    if (w >= N) return;
    int start = g_rowptr[w], end = g_rowptr[w + 1];
    int j0 = 2 * lane;
    int off = j0 < 46 ? j0 : 46;                     // clamped, even -> aligned float2
    bool m0 = (j0 < NCLS), m1 = (j0 + 1 < NCLS);

    float b0 = m0 ? bias2[j0] : 0.f;
    float b1 = m1 ? bias2[j0 + 1] : 0.f;
    if (start == end) {
        if (m0) out[(size_t)w * NCLS + j0] = b0;
        if (m1) out[(size_t)w * NCLS + j0 + 1] = b1;
        return;
    }
    float2 fdr = *(const float2*)&g_fd2[(size_t)w * NC2P + off];
    float fdv0 = m0 ? fdr.x : 0.f;
    float fdv1 = m1 ? fdr.y : 0.f;
    float att0 = m0 ? attn2[j0] : 0.f;
    float att1 = m1 ? attn2[j0 + 1] : 0.f;

    float mx = -INFINITY, s = 0.f;
    float acc0 = 0.f, acc1 = 0.f;

    for (int p = start; p < end; ++p) {
        int u = g_src_sorted[p];
        float2 fr = *(const float2*)&g_fs2[(size_t)u * NC2P + off];
        float f0 = m0 ? fr.x : 0.f;
        float f1 = m1 ? fr.y : 0.f;
        float t = lrelu(f0 + fdv0) * att0 + lrelu(f1 + fdv1) * att1;
        t += __shfl_xor_sync(0xffffffffu, t, 1);
        t += __shfl_xor_sync(0xffffffffu, t, 2);
        t += __shfl_xor_sync(0xffffffffu, t, 4);
        t += __shfl_xor_sync(0xffffffffu, t, 8);
        t += __shfl_xor_sync(0xffffffffu, t, 16);
        float ed = __expf(0.f - fabsf(t - mx));
        bool up = t > mx;
        float sc = up ? ed : 1.f;
        float wt = up ? 1.f : ed;
        mx = fmaxf(mx, t);
        s = fmaf(s, sc, wt);
        acc0 = fmaf(acc0, sc, wt * f0);
        acc1 = fmaf(acc1, sc, wt * f1);
    }
    float inv = 1.f / s;
    if (m0) out[(size_t)w * NCLS + j0]     = acc0 * inv + b0;
    if (m1) out[(size_t)w * NCLS + j0 + 1] = acc1 * inv + b1;
}

// ---------------- launch ----------------
extern "C" void kernel_launch(void* const* d_in, const int* in_sizes, int n_in,
                              void* d_out, int out_size) {
    const float* x      = (const float*)d_in[0];
    const void*  srcRaw = d_in[1];
    const void*  dstRaw = d_in[2];
    const float* W1s = (const float*)d_in[3];
    const float* b1s = (const float*)d_in[4];
    const float* W1d = (const float*)d_in[5];
    const float* b1d = (const float*)d_in[6];
    const float* attn1 = (const float*)d_in[7];
    const float* bias1 = (const float*)d_in[8];
    const float* W2s = (const float*)d_in[9];
    const float* b2s = (const float*)d_in[10];
    const float* W2d = (const float*)d_in[11];
    const float* b2d = (const float*)d_in[12];
    const float* attn2 = (const float*)d_in[13];
    const float* bias2 = (const float*)d_in[14];
    float* out = (float*)d_out;

    int N = in_sizes[0] / IN_DIM;   // 100000
    int E = in_sizes[1];            // 1600000
    int nb = (N + 1023) >> 10;      // scan blocks (98)

    detect_kernel<<<1, 1>>>((const int*)srcRaw);
    zero_deg_kernel<<<(N + 255) / 256, 256>>>(N);
    convert_hist_kernel<<<(E + 255) / 256, 256>>>(dstRaw, E);
    scan_phase1<<<nb, 1024>>>(N);
    scan_phase2<<<1, 128>>>(nb, N);
    scan_phase3<<<(N + 255) / 256, 256>>>(N);
    scatter_kernel<<<(E + 255) / 256, 256>>>(srcRaw, E);

    combine1_kernel<<<(IN_DIM * 2 * HID + 255) / 256, 256>>>(W1s, b1s, W1d, b1d);
    combine2_kernel<<<(HID * 2 * NCLS + 255) / 256, 256>>>(W2s, b2s, W2d, b2d);

    gemm1_tc_kernel<<<(N + 127) / 128, 256>>>(x, N);
    // layer1: 2 nodes per warp -> 16 nodes per 256-thread block
    layer1_kernel<<<(N + 15) / 16, 256>>>(N, attn1, bias1);
    gemm2_kernel<<<(N + 63) / 64, 256>>>(N);
    layer2_kernel<<<(N + 7) / 8, 256>>>(N, attn2, bias2, out);
}

// round 9
// speedup vs baseline: 1.0828x; 1.0414x over previous
#include <cuda_runtime.h>
#include <cuda_bf16.h>
#include <math.h>
#include <stdint.h>

// Problem constants (fixed instance)
#define NMAX   100000
#define EMAX   1600000
#define IN_DIM 256
#define HID    64      // HEADS*D1 = 8*8
#define HEADS  8
#define D1     8
#define NCLS   47
#define NC2P   48      // padded stride for layer-2 feature arrays
#define N2PAD  96      // padded output cols for gemm2 (2*47 -> 96)
#define NEG_SLOPE 0.2f

// ---------------- device scratch (static allocation; no cudaMalloc) ----------------
__device__ int   g_is64;
__device__ int   g_dst32[EMAX];
__device__ int   g_src_sorted[EMAX];
__device__ int   g_deg[NMAX];
__device__ int   g_rowptr[NMAX + 1];
__device__ int   g_cur[NMAX];
__device__ int   g_bsum[128];           // >= ceil(NMAX/1024)=98 block sums

__device__ float g_fs1[(size_t)NMAX * HID];
__device__ float g_fd1[(size_t)NMAX * HID];
__device__ float g_h  [(size_t)NMAX * HID];
__device__ float g_fs2[(size_t)NMAX * NC2P];
__device__ float g_fd2[(size_t)NMAX * NC2P];

__device__ float g_Wc1[IN_DIM * 2 * HID];       // [256][128], pre-rounded to tf32
__device__ float g_bc1[2 * HID];
__device__ float g_Wc2p[HID * N2PAD];           // [64][96], tf32, cols 94-95 zero
__device__ float g_bc2[2 * NCLS];

__device__ __forceinline__ float lrelu(float x) { return x > 0.f ? x : NEG_SLOPE * x; }
__device__ __forceinline__ float elu(float x)   { return x > 0.f ? x : expm1f(x); }
__device__ __forceinline__ float tf32r(float x) {
    uint32_t r; asm("cvt.rna.tf32.f32 %0, %1;" : "=r"(r) : "f"(x));
    return __uint_as_float(r);
}

// ---------------- zero deg + index dtype detection (merged) ----------------
__global__ void zero_deg_kernel(const int* __restrict__ srcW, int N) {
    int v = blockIdx.x * blockDim.x + threadIdx.x;
    if (v < N) g_deg[v] = 0;
    if (blockIdx.x == 0 && threadIdx.x == 0) {
        int ok64 = 1;
        #pragma unroll
        for (int i = 1; i < 16; i += 2) if (srcW[i] != 0) ok64 = 0;
        g_is64 = ok64;
    }
}

__global__ void convert_hist_kernel(const void* __restrict__ dstRaw, int E) {
    int e = blockIdx.x * blockDim.x + threadIdx.x;
    if (e >= E) return;
    int d = g_is64 ? (int)((const long long*)dstRaw)[e] : ((const int*)dstRaw)[e];
    g_dst32[e] = d;
    atomicAdd(&g_deg[d], 1);
}

// ---------------- 3-phase multi-block exclusive scan of g_deg -> g_rowptr ----------------
__global__ void scan_phase1(int N) {
    __shared__ int sh[1024];
    int t = threadIdx.x;
    int i = blockIdx.x * 1024 + t;
    int v = (i < N) ? g_deg[i] : 0;
    sh[t] = v;
    __syncthreads();
    #pragma unroll
    for (int off = 1; off < 1024; off <<= 1) {
        int x = (t >= off) ? sh[t - off] : 0;
        __syncthreads();
        sh[t] += x;
        __syncthreads();
    }
    if (i < N) g_rowptr[i] = sh[t] - v;
    if (t == 1023) g_bsum[blockIdx.x] = sh[1023];
}

__global__ void scan_phase2(int nb, int N) {
    __shared__ int sh[128];
    int t = threadIdx.x;
    int v = (t < nb) ? g_bsum[t] : 0;
    sh[t] = v;
    __syncthreads();
    #pragma unroll
    for (int off = 1; off < 128; off <<= 1) {
        int x = (t >= off) ? sh[t - off] : 0;
        __syncthreads();
        sh[t] += x;
        __syncthreads();
    }
    if (t < nb) g_bsum[t] = sh[t] - v;
    if (t == 127) g_rowptr[N] = sh[127];
}

__global__ void scan_phase3(int N) {
    int i = blockIdx.x * blockDim.x + threadIdx.x;
    if (i < N) {
        int r = g_rowptr[i] + g_bsum[i >> 10];
        g_rowptr[i] = r;
        g_cur[i] = r;
    }
}

__global__ void scatter_kernel(const void* __restrict__ srcRaw, int E) {
    int e = blockIdx.x * blockDim.x + threadIdx.x;
    if (e >= E) return;
    int s = g_is64 ? (int)((const long long*)srcRaw)[e] : ((const int*)srcRaw)[e];
    int d = g_dst32[e];
    int p = atomicAdd(&g_cur[d], 1);
    g_src_sorted[p] = s;
}

// ---------------- weight packing (both layers, one kernel; tf32 pre-round) ----------------
__global__ void combine_kernel(const float* __restrict__ W1s, const float* __restrict__ b1s,
                               const float* __restrict__ W1d, const float* __restrict__ b1d,
                               const float* __restrict__ W2s, const float* __restrict__ b2s,
                               const float* __restrict__ W2d, const float* __restrict__ b2d) {
    int i = blockIdx.x * blockDim.x + threadIdx.x;
    if (i < IN_DIM * 2 * HID) {
        int k = i / (2 * HID), c = i % (2 * HID);
        float v = (c < HID) ? W1s[k * HID + c] : W1d[k * HID + (c - HID)];
        g_Wc1[i] = tf32r(v);
    }
    if (i < 2 * HID) g_bc1[i] = (i < HID) ? b1s[i] : b1d[i - HID];
    if (i < HID * N2PAD) {
        int k = i / N2PAD, c = i % N2PAD;
        float v = (c < NCLS) ? W2s[k * NCLS + c]
                : (c < 2 * NCLS) ? W2d[k * NCLS + (c - NCLS)] : 0.f;
        g_Wc2p[i] = tf32r(v);
    }
    if (i < 2 * NCLS) g_bc2[i] = (i < NCLS) ? b2s[i] : b2d[i - NCLS];
}

// ---------------- GEMM 1 (TF32 TC, register-prefetch pipeline) ----------------
__global__ void gemm1_tc_kernel(const float* __restrict__ x, int M) {
    __shared__ float As[128][36];
    __shared__ float Bs[32][136];
    int tid  = threadIdx.x;
    int lane = tid & 31;
    int warp = tid >> 5;
    int row0 = blockIdx.x * 128;
    int warpRow = warp * 16;
    int gid = lane >> 2;
    int tig = lane & 3;

    float c[16][4];
    #pragma unroll
    for (int j = 0; j < 16; ++j)
        #pragma unroll
        for (int q = 0; q < 4; ++q) c[j][q] = 0.f;

    float4 ra[4], rb[4];
    // prefetch chunk 0
    #pragma unroll
    for (int i = 0; i < 4; ++i) {
        int id = tid * 4 + i;
        int r = id >> 3, q = id & 7;
        int grow = row0 + r;
        ra[i] = (grow < M) ? *(const float4*)(x + (size_t)grow * IN_DIM + q * 4)
                           : make_float4(0.f, 0.f, 0.f, 0.f);
        int rB = id >> 5, qB = id & 31;
        rb[i] = *(const float4*)&g_Wc1[rB * 128 + qB * 4];
    }

    for (int chunk = 0; chunk < 8; ++chunk) {
        // store prefetched regs to smem (A rounded to tf32)
        #pragma unroll
        for (int i = 0; i < 4; ++i) {
            int id = tid * 4 + i;
            int r = id >> 3, q = id & 7;
            float4 v = ra[i];
            v.x = tf32r(v.x); v.y = tf32r(v.y); v.z = tf32r(v.z); v.w = tf32r(v.w);
            *(float4*)&As[r][q * 4] = v;
            int rB = id >> 5, qB = id & 31;
            *(float4*)&Bs[rB][qB * 4] = rb[i];
        }
        __syncthreads();
        // prefetch next chunk (overlaps with mma below)
        if (chunk < 7) {
            int k0 = (chunk + 1) * 32;
            #pragma unroll
            for (int i = 0; i < 4; ++i) {
                int id = tid * 4 + i;
                int r = id >> 3, q = id & 7;
                int grow = row0 + r;
                ra[i] = (grow < M) ? *(const float4*)(x + (size_t)grow * IN_DIM + k0 + q * 4)
                                   : make_float4(0.f, 0.f, 0.f, 0.f);
                int rB = id >> 5, qB = id & 31;
                rb[i] = *(const float4*)&g_Wc1[(k0 + rB) * 128 + qB * 4];
            }
        }
        #pragma unroll
        for (int kk = 0; kk < 32; kk += 8) {
            uint32_t a[4];
            a[0] = __float_as_uint(As[warpRow + gid    ][kk + tig    ]);
            a[1] = __float_as_uint(As[warpRow + gid + 8][kk + tig    ]);
            a[2] = __float_as_uint(As[warpRow + gid    ][kk + tig + 4]);
            a[3] = __float_as_uint(As[warpRow + gid + 8][kk + tig + 4]);
            #pragma unroll
            for (int j = 0; j < 16; ++j) {
                uint32_t b[2];
                b[0] = __float_as_uint(Bs[kk + tig    ][j * 8 + gid]);
                b[1] = __float_as_uint(Bs[kk + tig + 4][j * 8 + gid]);
                asm("mma.sync.aligned.m16n8k8.row.col.f32.tf32.tf32.f32 "
                    "{%0,%1,%2,%3}, {%4,%5,%6,%7}, {%8,%9}, {%0,%1,%2,%3};"
                    : "+f"(c[j][0]), "+f"(c[j][1]), "+f"(c[j][2]), "+f"(c[j][3])
                    : "r"(a[0]), "r"(a[1]), "r"(a[2]), "r"(a[3]),
                      "r"(b[0]), "r"(b[1]));
            }
        }
        __syncthreads();
    }
    int r0 = row0 + warpRow + gid;
    int r1 = r0 + 8;
    #pragma unroll
    for (int j = 0; j < 16; ++j) {
        int cb = j * 8 + tig * 2;
        float2 bv = *(const float2*)&g_bc1[cb];
        if (r0 < M) {
            float2 v = make_float2(c[j][0] + bv.x, c[j][1] + bv.y);
            if (cb < HID) *(float2*)&g_fs1[(size_t)r0 * HID + cb] = v;
            else          *(float2*)&g_fd1[(size_t)r0 * HID + cb - HID] = v;
        }
        if (r1 < M) {
            float2 v = make_float2(c[j][2] + bv.x, c[j][3] + bv.y);
            if (cb < HID) *(float2*)&g_fs1[(size_t)r1 * HID + cb] = v;
            else          *(float2*)&g_fd1[(size_t)r1 * HID + cb - HID] = v;
        }
    }
}

// ---------------- GEMM 2 (TF32 TC): h[M,64] @ Wc2p[64,96] -> fs2|fd2 (stride 48) ----------------
__device__ __forceinline__ void g2_store(int row, int c, float v) {
    if (c >= 2 * NCLS) return;
    v += g_bc2[c];
    if (c < NCLS) g_fs2[(size_t)row * NC2P + c] = v;
    else          g_fd2[(size_t)row * NC2P + (c - NCLS)] = v;
}

__global__ void gemm2_tc_kernel(int M) {
    __shared__ float As[128][36];
    __shared__ float Bs[32][104];
    int tid  = threadIdx.x;
    int lane = tid & 31;
    int warp = tid >> 5;
    int row0 = blockIdx.x * 128;
    int warpRow = warp * 16;
    int gid = lane >> 2;
    int tig = lane & 3;

    float c[12][4];
    #pragma unroll
    for (int j = 0; j < 12; ++j)
        #pragma unroll
        for (int q = 0; q < 4; ++q) c[j][q] = 0.f;

    float4 ra[4], rb[3];
    // prefetch chunk 0 (k0 = 0)
    #pragma unroll
    for (int i = 0; i < 4; ++i) {
        int id = tid * 4 + i;
        int r = id >> 3, q = id & 7;
        int grow = row0 + r;
        ra[i] = (grow < M) ? *(const float4*)(g_h + (size_t)grow * HID + q * 4)
                           : make_float4(0.f, 0.f, 0.f, 0.f);
    }
    #pragma unroll
    for (int i = 0; i < 3; ++i) {           // B tile 32x96 = 768 float4
        int id = tid + i * 256;
        int r = id / 24, q = id % 24;
        rb[i] = *(const float4*)&g_Wc2p[r * N2PAD + q * 4];
    }

    #pragma unroll
    for (int chunk = 0; chunk < 2; ++chunk) {
        #pragma unroll
        for (int i = 0; i < 4; ++i) {
            int id = tid * 4 + i;
            int r = id >> 3, q = id & 7;
            float4 v = ra[i];
            v.x = tf32r(v.x); v.y = tf32r(v.y); v.z = tf32r(v.z); v.w = tf32r(v.w);
            *(float4*)&As[r][q * 4] = v;
        }
        #pragma unroll
        for (int i = 0; i < 3; ++i) {
            int id = tid + i * 256;
            int r = id / 24, q = id % 24;
            *(float4*)&Bs[r][q * 4] = rb[i];
        }
        __syncthreads();
        if (chunk == 0) {
            #pragma unroll
            for (int i = 0; i < 4; ++i) {
                int id = tid * 4 + i;
                int r = id >> 3, q = id & 7;
                int grow = row0 + r;
                ra[i] = (grow < M) ? *(const float4*)(g_h + (size_t)grow * HID + 32 + q * 4)
                                   : make_float4(0.f, 0.f, 0.f, 0.f);
            }
            #pragma unroll
            for (int i = 0; i < 3; ++i) {
                int id = tid + i * 256;
                int r = id / 24, q = id % 24;
                rb[i] = *(const float4*)&g_Wc2p[(32 + r) * N2PAD + q * 4];
            }
        }
        #pragma unroll
        for (int kk = 0; kk < 32; kk += 8) {
            uint32_t a[4];
            a[0] = __float_as_uint(As[warpRow + gid    ][kk + tig    ]);
            a[1] = __float_as_uint(As[warpRow + gid + 8][kk + tig    ]);
            a[2] = __float_as_uint(As[warpRow + gid    ][kk + tig + 4]);
            a[3] = __float_as_uint(As[warpRow + gid + 8][kk + tig + 4]);
            #pragma unroll
            for (int j = 0; j < 12; ++j) {
                uint32_t b[2];
                b[0] = __float_as_uint(Bs[kk + tig    ][j * 8 + gid]);
                b[1] = __float_as_uint(Bs[kk + tig + 4][j * 8 + gid]);
                asm("mma.sync.aligned.m16n8k8.row.col.f32.tf32.tf32.f32 "
                    "{%0,%1,%2,%3}, {%4,%5,%6,%7}, {%8,%9}, {%0,%1,%2,%3};"
                    : "+f"(c[j][0]), "+f"(c[j][1]), "+f"(c[j][2]), "+f"(c[j][3])
                    : "r"(a[0]), "r"(a[1]), "r"(a[2]), "r"(a[3]),
                      "r"(b[0]), "r"(b[1]));
            }
        }
        __syncthreads();
    }
    int r0 = row0 + warpRow + gid;
    int r1 = r0 + 8;
    #pragma unroll
    for (int j = 0; j < 12; ++j) {
        int cb = j * 8 + tig * 2;
        if (r0 < M) { g2_store(r0, cb, c[j][0]); g2_store(r0, cb + 1, c[j][1]); }
        if (r1 < M) { g2_store(r1, cb, c[j][2]); g2_store(r1, cb + 1, c[j][3]); }
    }
}

// ---------------- layer 1: HALF-warp per node, 4 dims/lane (float4), head = 2 lanes ----------------
__global__ void layer1_kernel(int N, const float* __restrict__ attn1,
                              const float* __restrict__ bias1) {
    int gwarp = (blockIdx.x * blockDim.x + threadIdx.x) >> 5;
    int lane  = threadIdx.x & 31;
    int half  = lane >> 4;                   // 0 or 1
    int l16   = lane & 15;
    int w     = gwarp * 2 + half;
    if (w >= N) return;
    unsigned hmask = half ? 0xFFFF0000u : 0x0000FFFFu;
    int start = g_rowptr[w], end = g_rowptr[w + 1];
    int j0 = 4 * l16;                        // dims j0..j0+3 (head = l16>>1)

    float4 bv = *(const float4*)&bias1[j0];
    if (start == end) {
        float4 o = make_float4(elu(bv.x), elu(bv.y), elu(bv.z), elu(bv.w));
        *(float4*)&g_h[(size_t)w * HID + j0] = o;
        return;
    }
    float4 fdv = *(const float4*)&g_fd1[(size_t)w * HID + j0];
    float4 att = *(const float4*)&attn1[j0];

    float mx = -INFINITY, s = 0.f;
    float ax = 0.f, ay = 0.f, az = 0.f, aw = 0.f;

    for (int p = start; p < end; ++p) {
        int u = g_src_sorted[p];
        float4 f = *(const float4*)&g_fs1[(size_t)u * HID + j0];
        float t = lrelu(f.x + fdv.x) * att.x + lrelu(f.y + fdv.y) * att.y
                + lrelu(f.z + fdv.z) * att.z + lrelu(f.w + fdv.w) * att.w;
        t += __shfl_xor_sync(hmask, t, 1);   // head score (2 lanes per head)
        float ed = __expf(0.f - fabsf(t - mx));
        bool up = t > mx;
        float sc = up ? ed : 1.f;
        float wt = up ? 1.f : ed;
        mx = fmaxf(mx, t);
        s = fmaf(s, sc, wt);
        ax = fmaf(ax, sc, wt * f.x);
        ay = fmaf(ay, sc, wt * f.y);
        az = fmaf(az, sc, wt * f.z);
        aw = fmaf(aw, sc, wt * f.w);
    }
    float inv = 1.f / s;
    float4 o = make_float4(elu(ax * inv + bv.x), elu(ay * inv + bv.y),
                           elu(az * inv + bv.z), elu(aw * inv + bv.w));
    *(float4*)&g_h[(size_t)w * HID + j0] = o;
}

// ---------------- layer 2: warp/node, 2 classes per lane (padded stride 48) ----------------
__global__ void layer2_kernel(int N, const float* __restrict__ attn2,
                              const float* __restrict__ bias2,
                              float* __restrict__ out) {
    int w = (blockIdx.x * blockDim.x + threadIdx.x) >> 5;
    int lane = threadIdx.x & 31;
    if (w >= N) return;
    int start = g_rowptr[w], end = g_rowptr[w + 1];
    int j0 = 2 * lane;
    int off = j0 < 46 ? j0 : 46;                     // clamped, even -> aligned float2
    bool m0 = (j0 < NCLS), m1 = (j0 + 1 < NCLS);

    float b0 = m0 ? bias2[j0] : 0.f;
    float b1 = m1 ? bias2[j0 + 1] : 0.f;
    if (start == end) {
        if (m0) out[(size_t)w * NCLS + j0] = b0;
        if (m1) out[(size_t)w * NCLS + j0 + 1] = b1;
        return;
    }
    float2 fdr = *(const float2*)&g_fd2[(size_t)w * NC2P + off];
    float fdv0 = m0 ? fdr.x : 0.f;
    float fdv1 = m1 ? fdr.y : 0.f;
    float att0 = m0 ? attn2[j0] : 0.f;
    float att1 = m1 ? attn2[j0 + 1] : 0.f;

    float mx = -INFINITY, s = 0.f;
    float acc0 = 0.f, acc1 = 0.f;

    for (int p = start; p < end; ++p) {
        int u = g_src_sorted[p];
        float2 fr = *(const float2*)&g_fs2[(size_t)u * NC2P + off];
        float f0 = m0 ? fr.x : 0.f;
        float f1 = m1 ? fr.y : 0.f;
        float t = lrelu(f0 + fdv0) * att0 + lrelu(f1 + fdv1) * att1;
        t += __shfl_xor_sync(0xffffffffu, t, 1);
        t += __shfl_xor_sync(0xffffffffu, t, 2);
        t += __shfl_xor_sync(0xffffffffu, t, 4);
        t += __shfl_xor_sync(0xffffffffu, t, 8);
        t += __shfl_xor_sync(0xffffffffu, t, 16);
        float ed = __expf(0.f - fabsf(t - mx));
        bool up = t > mx;
        float sc = up ? ed : 1.f;
        float wt = up ? 1.f : ed;
        mx = fmaxf(mx, t);
        s = fmaf(s, sc, wt);
        acc0 = fmaf(acc0, sc, wt * f0);
        acc1 = fmaf(acc1, sc, wt * f1);
    }
    float inv = 1.f / s;
    if (m0) out[(size_t)w * NCLS + j0]     = acc0 * inv + b0;
    if (m1) out[(size_t)w * NCLS + j0 + 1] = acc1 * inv + b1;
}

// ---------------- launch ----------------
extern "C" void kernel_launch(void* const* d_in, const int* in_sizes, int n_in,
                              void* d_out, int out_size) {
    const float* x      = (const float*)d_in[0];
    const void*  srcRaw = d_in[1];
    const void*  dstRaw = d_in[2];
    const float* W1s = (const float*)d_in[3];
    const float* b1s = (const float*)d_in[4];
    const float* W1d = (const float*)d_in[5];
    const float* b1d = (const float*)d_in[6];
    const float* attn1 = (const float*)d_in[7];
    const float* bias1 = (const float*)d_in[8];
    const float* W2s = (const float*)d_in[9];
    const float* b2s = (const float*)d_in[10];
    const float* W2d = (const float*)d_in[11];
    const float* b2d = (const float*)d_in[12];
    const float* attn2 = (const float*)d_in[13];
    const float* bias2 = (const float*)d_in[14];
    float* out = (float*)d_out;

    int N = in_sizes[0] / IN_DIM;   // 100000
    int E = in_sizes[1];            // 1600000
    int nb = (N + 1023) >> 10;      // scan blocks (98)

    zero_deg_kernel<<<(N + 255) / 256, 256>>>((const int*)srcRaw, N);
    convert_hist_kernel<<<(E + 255) / 256, 256>>>(dstRaw, E);
    scan_phase1<<<nb, 1024>>>(N);
    scan_phase2<<<1, 128>>>(nb, N);
    scan_phase3<<<(N + 255) / 256, 256>>>(N);
    scatter_kernel<<<(E + 255) / 256, 256>>>(srcRaw, E);

    combine_kernel<<<(IN_DIM * 2 * HID + 255) / 256, 256>>>(W1s, b1s, W1d, b1d,
                                                            W2s, b2s, W2d, b2d);

    gemm1_tc_kernel<<<(N + 127) / 128, 256>>>(x, N);
    layer1_kernel<<<(N + 15) / 16, 256>>>(N, attn1, bias1);
    gemm2_tc_kernel<<<(N + 127) / 128, 256>>>(N);
    layer2_kernel<<<(N + 7) / 8, 256>>>(N, attn2, bias2, out);
}